// round 14
// baseline (speedup 1.0000x reference)
#include <cuda_runtime.h>
#include <math.h>

#define B 256
#define T 2048
#define V 64
#define H 64
#define EOS 2

#if defined(__CUDA_ARCH__) && defined(__CUDA_ARCH_FEAT_SM103_ALL)
#define TC_PATH 1
#else
#define TC_PATH 0
#endif

// Precomputed tables
__device__ float g_gtable[V * 4];
__device__ float g_quad[14 * V];                      // scalar-fallback head coeffs
__device__ __align__(16) unsigned int g_Bimg[2048];   // 8KB bf16 B-operand image (SW128)

// ---------------- SMEM layout (dynamic) ----------------
#define OFF_C    0        // Cbuf: float4[2048]  (32768)
#define OFF_A    32768    // A tile: 128 rows x 128B (16384)
#define OFF_B    49152    // B tile: 64 rows x 128B  (8192)
#define OFF_S    57344    // staging: float4[16*129] (33024)
#define OFF_SB   90368    // sbuf: float[2048] (8192)
#define OFF_GT   98560    // gt: float4[64] (1024)
#define OFF_WT   99584    // warp_tot: float4[8] (128)
#define OFF_CTRL 99712    // [0]=tmem ptr, [8]=mbar
#define SMEM_TOTAL 99728

#define IDESC 0x8100490u  // kind::f16, bf16 x bf16 -> f32, M=128, N=64, K-major both

// ---------------- generic helpers ----------------
__device__ __forceinline__ unsigned int smem_u32(const void* p) {
    unsigned int a;
    asm("{ .reg .u64 t; cvta.to.shared.u64 t, %1; cvt.u32.u64 %0, t; }" : "=r"(a) : "l"(p));
    return a;
}
__device__ __forceinline__ unsigned int bf16pair(float lo_v, float hi_v) {
    unsigned int r;
    asm("cvt.rn.satfinite.bf16x2.f32 %0, %1, %2;" : "=r"(r) : "f"(hi_v), "f"(lo_v));
    return r;
}
__device__ __forceinline__ float trunc16(float x) {
    return __uint_as_float(__float_as_uint(x) & 0xFFFF0000u);
}
__device__ __forceinline__ float gelu_exact(float x) {
    return 0.5f * x * (1.0f + erff(x * 0.70710678118654752440f));
}
__device__ __forceinline__ float4 qmul(float4 a, float4 b) {
    float4 r;
    r.x = a.x * b.x - a.y * b.y - a.z * b.z - a.w * b.w;
    r.y = a.x * b.y + a.y * b.x + a.z * b.w - a.w * b.z;
    r.z = a.x * b.z - a.y * b.w + a.z * b.x + a.w * b.y;
    r.w = a.x * b.w + a.y * b.z - a.z * b.y + a.w * b.x;
    return r;
}
__device__ __forceinline__ float4 qnorm(float4 q) {
    float n2 = q.x * q.x + q.y * q.y + q.z * q.z + q.w * q.w;
    float inv = rsqrtf(fmaxf(n2, 1e-24f));
    q.x *= inv; q.y *= inv; q.z *= inv; q.w *= inv;
    return q;
}
__device__ __forceinline__ float4 shfl_up4(float4 v, int d) {
    float4 r;
    r.x = __shfl_up_sync(0xFFFFFFFFu, v.x, d);
    r.y = __shfl_up_sync(0xFFFFFFFFu, v.y, d);
    r.z = __shfl_up_sync(0xFFFFFFFFu, v.z, d);
    r.w = __shfl_up_sync(0xFFFFFFFFu, v.w, d);
    return r;
}
__device__ __forceinline__ float wred(float p) {
    #pragma unroll
    for (int off = 16; off > 0; off >>= 1) p += __shfl_down_sync(0xFFFFFFFFu, p, off);
    return p;
}
__device__ __forceinline__ void stcs4(float* p, float4 v) {
    asm volatile("st.global.cs.v4.f32 [%0], {%1,%2,%3,%4};"
                 :: "l"(p), "f"(v.x), "f"(v.y), "f"(v.z), "f"(v.w) : "memory");
}
__device__ __forceinline__ float acos_poly(float u) {
    float p = fmaf(u, -0.0012624911f, 0.0066700901f);
    p = fmaf(u, p, -0.0170881256f);
    p = fmaf(u, p,  0.0308918810f);
    p = fmaf(u, p, -0.0501743046f);
    p = fmaf(u, p,  0.0889789874f);
    p = fmaf(u, p, -0.2145988016f);
    p = fmaf(u, p,  1.5707963050f);
    return sqrtf(1.0f - u) * p;
}
__device__ __forceinline__ float sig_from_w(float wv) {
    return acos_poly(fminf(fabsf(wv), 1.0f - 1e-7f));
}

#if TC_PATH
// ---------------- tcgen05 helpers (sm_103a-only pass) ----------------
__device__ __forceinline__ unsigned int elect1() {
    unsigned int p;
    asm volatile("{ .reg .pred p; elect.sync _|p, 0xFFFFFFFF; selp.b32 %0, 1, 0, p; }" : "=r"(p));
    return p;
}
__device__ __forceinline__ void sts32(unsigned int a, unsigned int v) {
    asm volatile("st.shared.b32 [%0], %1;" :: "r"(a), "r"(v) : "memory");
}
__device__ __forceinline__ void mbar_init(unsigned int a) {
    asm volatile("mbarrier.init.shared.b64 [%0], %1;" :: "r"(a), "r"(1u) : "memory");
}
__device__ __forceinline__ void mbar_wait(unsigned int a, unsigned int par) {
    asm volatile("{\n\t.reg .pred P1;\n\tW%=:\n\t"
                 "mbarrier.try_wait.parity.acquire.cta.shared::cta.b64 P1, [%0], %1, 0x989680;\n\t"
                 "@P1 bra D%=;\n\tbra W%=;\n\tD%=:\n\t}"
                 :: "r"(a), "r"(par) : "memory");
}
__device__ __forceinline__ void mma_f16_ss(unsigned int d, unsigned long long ad,
                                           unsigned long long bd, unsigned int en) {
    asm volatile("{\n\t.reg .pred p;\n\tsetp.ne.u32 p, %5, 0;\n\t"
                 "tcgen05.mma.cta_group::1.kind::f16 [%0], %1, %2, %3, {%4,%4,%4,%4}, p;\n\t}"
                 :: "r"(d), "l"(ad), "l"(bd), "r"(IDESC), "r"(0u), "r"(en) : "memory");
}
__device__ __forceinline__ void tc_commit(unsigned int mbar) {
    asm volatile("tcgen05.commit.cta_group::1.mbarrier::arrive::one.shared::cluster.b64 [%0];"
                 :: "r"(mbar) : "memory");
}
#define TC_FENCE_AFTER()  asm volatile("tcgen05.fence::after_thread_sync;" ::: "memory")
#define TC_WAIT_LD()      asm volatile("tcgen05.wait::ld.sync.aligned;" ::: "memory")
#define FENCE_ASYNC()     asm volatile("fence.proxy.async.shared::cta;" ::: "memory")

#define LDTM_X32(r, addr) \
    asm volatile("tcgen05.ld.sync.aligned.32x32b.x32.b32 " \
        "{%0,%1,%2,%3,%4,%5,%6,%7,%8,%9,%10,%11,%12,%13,%14,%15," \
        "%16,%17,%18,%19,%20,%21,%22,%23,%24,%25,%26,%27,%28,%29,%30,%31}, [%32];" \
        : "=r"((r)[0]),"=r"((r)[1]),"=r"((r)[2]),"=r"((r)[3]),"=r"((r)[4]),"=r"((r)[5]), \
          "=r"((r)[6]),"=r"((r)[7]),"=r"((r)[8]),"=r"((r)[9]),"=r"((r)[10]),"=r"((r)[11]), \
          "=r"((r)[12]),"=r"((r)[13]),"=r"((r)[14]),"=r"((r)[15]),"=r"((r)[16]),"=r"((r)[17]), \
          "=r"((r)[18]),"=r"((r)[19]),"=r"((r)[20]),"=r"((r)[21]),"=r"((r)[22]),"=r"((r)[23]), \
          "=r"((r)[24]),"=r"((r)[25]),"=r"((r)[26]),"=r"((r)[27]),"=r"((r)[28]),"=r"((r)[29]), \
          "=r"((r)[30]),"=r"((r)[31]) : "r"(addr))
#endif  // TC_PATH

// ---------------------------------------------------------------------------
// Kernel 1 (precompute), 128 blocks x 64 threads.
//  blocks [0,64):  g table
//  blocks [64,128): quadratic head coeffs -> g_quad (fallback) + g_Bimg (tensor)
// ---------------------------------------------------------------------------
__global__ void precompute_kernel(const float* __restrict__ eW1,
                                  const float* __restrict__ eb1,
                                  const float* __restrict__ eW2,
                                  const float* __restrict__ eb2,
                                  const float* __restrict__ hW1,
                                  const float* __restrict__ hb1,
                                  const float* __restrict__ hW2,
                                  const float* __restrict__ hb2) {
    int blk = blockIdx.x;
    int j = threadIdx.x;
    int lane = j & 31, w = j >> 5;

    if (blk < 64) {
        int v = blk;
        float x = eW1[v * H + j] + eb1[j];
        float h = gelu_exact(x);
        float p0 = wred(h * eW2[j * 4 + 0]);
        float p1 = wred(h * eW2[j * 4 + 1]);
        float p2 = wred(h * eW2[j * 4 + 2]);
        float p3 = wred(h * eW2[j * 4 + 3]);
        __shared__ float red[2][4];
        if (lane == 0) { red[w][0] = p0; red[w][1] = p1; red[w][2] = p2; red[w][3] = p3; }
        __syncthreads();
        if (j == 0) {
            float a0 = red[0][0] + red[1][0] + eb2[0];
            float a1 = red[0][1] + red[1][1] + eb2[1];
            float a2 = red[0][2] + red[1][2] + eb2[2];
            float a3 = red[0][3] + red[1][3] + eb2[3];
            float n = sqrtf(a0 * a0 + a1 * a1 + a2 * a2 + a3 * a3);
            float inv = 1.0f / fmaxf(n, 1e-12f);
            float4 g = make_float4(a0 * inv, a1 * inv, a2 * inv, a3 * inv);
            if (v == EOS) g = make_float4(1.0f, 0.0f, 0.0f, 0.0f);
            reinterpret_cast<float4*>(g_gtable)[v] = g;
        }
    } else {
        int v = blk - 64;
        float b  = hb1[j];
        float wv = hW2[j * V + v];
        float w0 = hW1[0 * H + j], w1 = hW1[1 * H + j];
        float w2 = hW1[2 * H + j], w3 = hW1[3 * H + j];
        float sig2 = 0.25f * (w0 * w0 + w1 * w1 + w2 * w2 + w3 * w3);
        float phi = 0.3989422804014327f * expf(-0.5f * b * b);
        float cdf = 0.5f * (1.0f + erff(b * 0.70710678118654752f));
        float g0 = b * cdf;
        float g1 = cdf + b * phi;
        float g2 = 0.5f * (2.0f - b * b) * phi;
        float g3 = -b * (4.0f - b * b) * phi * (1.0f / 6.0f);
        float b2 = b * b;
        float g4 = (-4.0f + 7.0f * b2 - b2 * b2) * phi * (1.0f / 24.0f);
        float e1 = g1 + 3.0f * sig2 * g3;
        float e2 = g2 + 3.0f * sig2 * g4;

        float c[15];
        c[0] = wv * g0;
        float l = wv * e1;
        c[1] = l * w0; c[2] = l * w1; c[3] = l * w2; c[4] = l * w3;
        float q = wv * e2;
        c[5]  = q * w0 * w0;        c[6]  = 2.0f * q * w0 * w1;
        c[7]  = 2.0f * q * w0 * w2; c[8]  = 2.0f * q * w0 * w3;
        c[9]  = q * w1 * w1;        c[10] = 2.0f * q * w1 * w2;
        c[11] = 2.0f * q * w1 * w3; c[12] = q * w2 * w2;
        c[13] = 2.0f * q * w2 * w3; c[14] = q * w3 * w3;

        __shared__ float redq[2][15];
        float tot[15];
        #pragma unroll
        for (int s = 0; s < 15; s++) {
            float r = wred(c[s]);
            if (lane == 0) redq[w][s] = r;
        }
        __syncthreads();
        if (j == 0) {
            #pragma unroll
            for (int s = 0; s < 15; s++) tot[s] = redq[0][s] + redq[1][s];
            tot[0] += hb2[v];
            // fold z^2 slot via |C|=1 (exact)
            tot[0]  += tot[14];
            tot[5]  -= tot[14];
            tot[9]  -= tot[14];
            tot[12] -= tot[14];

            // scalar-fallback coefficient table
            #pragma unroll
            for (int s = 0; s < 14; s++) g_quad[s * V + v] = tot[s];

            // tensor B image row v: 128 bytes, SW128 swizzled, bf16 pairs
            // slots [0..13]=Qhi, [14..27]=Qlo, [28..41]=Qhi, rest 0
            unsigned int* img = g_Bimg + v * 32;
            #pragma unroll
            for (int u = 0; u < 32; u++) img[u] = 0u;
            unsigned int mask = (unsigned)(v & 7) << 4;
            #pragma unroll
            for (int p = 0; p < 7; p++) {
                float a0 = tot[2 * p], a1 = tot[2 * p + 1];
                unsigned int hp = __byte_perm(__float_as_uint(a0), __float_as_uint(a1), 0x7632);
                unsigned int lp = bf16pair(a0 - trunc16(a0), a1 - trunc16(a1));
                img[((p * 4) ^ mask) >> 2]      = hp;
                img[((28 + p * 4) ^ mask) >> 2] = lp;
                img[((56 + p * 4) ^ mask) >> 2] = hp;
            }
        }
    }
}

// ---------------------------------------------------------------------------
// Kernel 2 (fused): scan (R12-proven) + head.
// TC_PATH: tcgen05 bf16-split GEMM head.  Else: R12 scalar FFMA head.
// ---------------------------------------------------------------------------
extern __shared__ __align__(1024) char dynsmem[];

__global__ __launch_bounds__(256, 2)
void fused_kernel(const int* __restrict__ tokens,
                  float* __restrict__ logits,
                  float* __restrict__ sigmas) {
    float4* Cbuf = reinterpret_cast<float4*>(dynsmem + OFF_C);
    float*  sbuf = reinterpret_cast<float*>(dynsmem + OFF_SB);
    float4* gt   = reinterpret_cast<float4*>(dynsmem + OFF_GT);
    float4* warp_tot = reinterpret_cast<float4*>(dynsmem + OFF_WT);

    int b = blockIdx.x;
    int t = threadIdx.x;
    int lane = t & 31;
    int w = t >> 5;

#if TC_PATH
    float4* stg = reinterpret_cast<float4*>(dynsmem + OFF_S);
    unsigned int ctrl = smem_u32(dynsmem + OFF_CTRL);
    unsigned int abuf_u = smem_u32(dynsmem + OFF_A);

    if (t == 0) mbar_init(ctrl + 8);
    if (w == 0) {
        asm volatile("tcgen05.alloc.cta_group::1.sync.aligned.shared::cta.b32 [%0], %1;"
                     :: "r"(ctrl), "r"(64u) : "memory");
        asm volatile("tcgen05.relinquish_alloc_permit.cta_group::1.sync.aligned;");
    }
    {
        uint4 z = make_uint4(0, 0, 0, 0);
        uint4* ab4 = reinterpret_cast<uint4*>(dynsmem + OFF_A);
        #pragma unroll
        for (int k2 = 0; k2 < 4; k2++) ab4[t + k2 * 256] = z;
        const uint4* bi = reinterpret_cast<const uint4*>(g_Bimg);
        uint4* bb4 = reinterpret_cast<uint4*>(dynsmem + OFF_B);
        bb4[t] = bi[t];
        bb4[t + 256] = bi[t + 256];
    }
#endif
    if (t < V) gt[t] = reinterpret_cast<const float4*>(g_gtable)[t];
    __syncthreads();

#if TC_PATH
    unsigned int tmem_base;
    asm volatile("ld.shared.b32 %0, [%1];" : "=r"(tmem_base) : "r"(ctrl));
#endif

    // ---- Phase A: scan (8 tokens per thread) ----
    const int4* tp = reinterpret_cast<const int4*>(tokens + b * T + t * 8);
    int4 ta = tp[0];
    int4 tb = tp[1];
    int tok[8] = {ta.x, ta.y, ta.z, ta.w, tb.x, tb.y, tb.z, tb.w};

    float4 P = gt[tok[0]];
    #pragma unroll
    for (int i = 1; i < 8; i++) P = qmul(P, gt[tok[i]]);

    #pragma unroll
    for (int off = 1; off < 32; off <<= 1) {
        float4 o = shfl_up4(P, off);
        if (lane >= off) P = qmul(o, P);
    }

    if (lane == 31) warp_tot[w] = P;
    float4 laneExcl = shfl_up4(P, 1);
    __syncthreads();

    float4 E = make_float4(1.0f, 0.0f, 0.0f, 0.0f);
    for (int i = 0; i < w; i++) E = qmul(E, warp_tot[i]);
    if (lane > 0) E = qmul(E, laneExcl);
    E = qnorm(E);

    float4 C = E;
    #pragma unroll
    for (int i = 0; i < 8; i++) {
        C = qnorm(qmul(C, gt[tok[i]]));
        Cbuf[i * 256 + t] = C;
        sbuf[t * 8 + i] = C.x;
    }
    __syncthreads();

#if TC_PATH
    // ---- Phase B (tensor): 16 tiles of M=128 x N=64 ----
    const unsigned long long DESCBASE =
        (2ull << 61) | (1ull << 46) | (64ull << 32) | (1ull << 16);  // SW128, v1, SBO=64, LBO=1
    unsigned long long adesc = DESCBASE | ((unsigned long long)((abuf_u >> 4) & 0x3FFF));
    unsigned long long bdesc = DESCBASE | ((unsigned long long)((smem_u32(dynsmem + OFF_B) >> 4) & 0x3FFF));

    int row_l = t & 127;
    int halfsel = t >> 7;
    unsigned int arow = abuf_u + row_l * 128;
    unsigned int amask = (unsigned)(row_l & 7) << 4;

    for (int tile = 0; tile < 16; tile++) {
        // gen: write A tile (bf16 split, SW128 swizzled)
        {
            int gr = tile * 128 + row_l;
            float4 Cr = Cbuf[(gr & 7) * 256 + (gr >> 3)];
            float m[14];
            m[0] = 1.0f; m[1] = Cr.x; m[2] = Cr.y; m[3] = Cr.z; m[4] = Cr.w;
            m[5] = Cr.x * Cr.x;  m[6] = Cr.x * Cr.y;  m[7] = Cr.x * Cr.z;  m[8] = Cr.x * Cr.w;
            m[9] = Cr.y * Cr.y;  m[10] = Cr.y * Cr.z; m[11] = Cr.y * Cr.w;
            m[12] = Cr.z * Cr.z; m[13] = Cr.z * Cr.w;
            if (halfsel == 0) {
                #pragma unroll
                for (int p = 0; p < 7; p++) {
                    unsigned int hp = __byte_perm(__float_as_uint(m[2 * p]),
                                                  __float_as_uint(m[2 * p + 1]), 0x7632);
                    sts32(arow + ((unsigned)(p * 4) ^ amask), hp);
                    sts32(arow + ((unsigned)(28 + p * 4) ^ amask), hp);
                }
            } else {
                #pragma unroll
                for (int p = 0; p < 7; p++) {
                    float a0 = m[2 * p], a1 = m[2 * p + 1];
                    unsigned int lp = bf16pair(a0 - trunc16(a0), a1 - trunc16(a1));
                    sts32(arow + ((unsigned)(56 + p * 4) ^ amask), lp);
                }
            }
        }
        FENCE_ASYNC();
        __syncthreads();

        if (w == 0 && elect1()) {
            mma_f16_ss(tmem_base, adesc, bdesc, 0u);
            mma_f16_ss(tmem_base, adesc + 2, bdesc + 2, 1u);
            mma_f16_ss(tmem_base, adesc + 4, bdesc + 4, 1u);
            tc_commit(ctrl + 8);
        }

        if (w < 4) {
            mbar_wait(ctrl + 8, (unsigned)(tile & 1));
            TC_FENCE_AFTER();
            int row_d = w * 32 + lane;
            unsigned int dr[32];
            LDTM_X32(dr, tmem_base);
            TC_WAIT_LD();
            #pragma unroll
            for (int c4 = 0; c4 < 8; c4++)
                stg[c4 * 129 + row_d] = make_float4(
                    __uint_as_float(dr[4 * c4 + 0]), __uint_as_float(dr[4 * c4 + 1]),
                    __uint_as_float(dr[4 * c4 + 2]), __uint_as_float(dr[4 * c4 + 3]));
            LDTM_X32(dr, tmem_base + 32);
            TC_WAIT_LD();
            #pragma unroll
            for (int c4 = 0; c4 < 8; c4++)
                stg[(c4 + 8) * 129 + row_d] = make_float4(
                    __uint_as_float(dr[4 * c4 + 0]), __uint_as_float(dr[4 * c4 + 1]),
                    __uint_as_float(dr[4 * c4 + 2]), __uint_as_float(dr[4 * c4 + 3]));
        }
        __syncthreads();

        {
            long rowbase = (long)b * T + tile * 128;
            #pragma unroll
            for (int k2 = 0; k2 < 8; k2++) {
                int idx = t + k2 * 256;
                int r = idx >> 4, cc = idx & 15;
                float4 v = stg[cc * 129 + r];
                stcs4(logits + (rowbase + r) * V + cc * 4, v);
            }
        }
        __syncthreads();
    }
#else
    // ---- Phase B (scalar fallback, R12-proven) ----
    int col = lane & 15;
    int half = lane >> 4;

    float4 cf[14];
    const float4* gq = reinterpret_cast<const float4*>(g_quad);
    #pragma unroll
    for (int s = 0; s < 14; s++) cf[s] = gq[s * 16 + col];

    int rlow = (w * 2 + half) & 7;
    int rhigh = (w * 2 + half) >> 3;
    const float4* cbase = Cbuf + rlow * 256 + rhigh;
    float* outp = logits + (long)b * T * V + (long)(w * 2 + half) * V + col * 4;

    #pragma unroll 4
    for (int i = 0; i < 128; i++) {
        float4 Cr = cbase[i * 2];

        float m4  = Cr.x * Cr.x, m5  = Cr.x * Cr.y, m6  = Cr.x * Cr.z, m7 = Cr.x * Cr.w;
        float m8  = Cr.y * Cr.y, m9  = Cr.y * Cr.z, m10 = Cr.y * Cr.w;
        float m11 = Cr.z * Cr.z, m12 = Cr.z * Cr.w;

        float4 a = cf[0];
        a.x = fmaf(Cr.x, cf[1].x, a.x);  a.y = fmaf(Cr.x, cf[1].y, a.y);
        a.z = fmaf(Cr.x, cf[1].z, a.z);  a.w = fmaf(Cr.x, cf[1].w, a.w);
        a.x = fmaf(Cr.y, cf[2].x, a.x);  a.y = fmaf(Cr.y, cf[2].y, a.y);
        a.z = fmaf(Cr.y, cf[2].z, a.z);  a.w = fmaf(Cr.y, cf[2].w, a.w);
        a.x = fmaf(Cr.z, cf[3].x, a.x);  a.y = fmaf(Cr.z, cf[3].y, a.y);
        a.z = fmaf(Cr.z, cf[3].z, a.z);  a.w = fmaf(Cr.z, cf[3].w, a.w);
        a.x = fmaf(Cr.w, cf[4].x, a.x);  a.y = fmaf(Cr.w, cf[4].y, a.y);
        a.z = fmaf(Cr.w, cf[4].z, a.z);  a.w = fmaf(Cr.w, cf[4].w, a.w);
        a.x = fmaf(m4,  cf[5].x, a.x);   a.y = fmaf(m4,  cf[5].y, a.y);
        a.z = fmaf(m4,  cf[5].z, a.z);   a.w = fmaf(m4,  cf[5].w, a.w);
        a.x = fmaf(m5,  cf[6].x, a.x);   a.y = fmaf(m5,  cf[6].y, a.y);
        a.z = fmaf(m5,  cf[6].z, a.z);   a.w = fmaf(m5,  cf[6].w, a.w);
        a.x = fmaf(m6,  cf[7].x, a.x);   a.y = fmaf(m6,  cf[7].y, a.y);
        a.z = fmaf(m6,  cf[7].z, a.z);   a.w = fmaf(m6,  cf[7].w, a.w);
        a.x = fmaf(m7,  cf[8].x, a.x);   a.y = fmaf(m7,  cf[8].y, a.y);
        a.z = fmaf(m7,  cf[8].z, a.z);   a.w = fmaf(m7,  cf[8].w, a.w);
        a.x = fmaf(m8,  cf[9].x, a.x);   a.y = fmaf(m8,  cf[9].y, a.y);
        a.z = fmaf(m8,  cf[9].z, a.z);   a.w = fmaf(m8,  cf[9].w, a.w);
        a.x = fmaf(m9,  cf[10].x, a.x);  a.y = fmaf(m9,  cf[10].y, a.y);
        a.z = fmaf(m9,  cf[10].z, a.z);  a.w = fmaf(m9,  cf[10].w, a.w);
        a.x = fmaf(m10, cf[11].x, a.x);  a.y = fmaf(m10, cf[11].y, a.y);
        a.z = fmaf(m10, cf[11].z, a.z);  a.w = fmaf(m10, cf[11].w, a.w);
        a.x = fmaf(m11, cf[12].x, a.x);  a.y = fmaf(m11, cf[12].y, a.y);
        a.z = fmaf(m11, cf[12].z, a.z);  a.w = fmaf(m11, cf[12].w, a.w);
        a.x = fmaf(m12, cf[13].x, a.x);  a.y = fmaf(m12, cf[13].y, a.y);
        a.z = fmaf(m12, cf[13].z, a.z);  a.w = fmaf(m12, cf[13].w, a.w);

        stcs4(outp + (long)i * 16 * V, a);
    }
#endif

    // ---- sigmas: acos at copy-out ----
    {
        const float4* sb4 = reinterpret_cast<const float4*>(sbuf);
        float* so = sigmas + (long)b * T;
        float4 s0 = sb4[t];
        float4 s1 = sb4[t + 256];
        s0.x = sig_from_w(s0.x); s0.y = sig_from_w(s0.y);
        s0.z = sig_from_w(s0.z); s0.w = sig_from_w(s0.w);
        s1.x = sig_from_w(s1.x); s1.y = sig_from_w(s1.y);
        s1.z = sig_from_w(s1.z); s1.w = sig_from_w(s1.w);
        stcs4(so + t * 4, s0);
        stcs4(so + 1024 + t * 4, s1);
    }

#if TC_PATH
    __syncthreads();
    if (w == 0) {
        asm volatile("tcgen05.dealloc.cta_group::1.sync.aligned.b32 %0, %1;"
                     :: "r"(tmem_base), "r"(64u));
    }
#endif
}

// ---------------------------------------------------------------------------
extern "C" void kernel_launch(void* const* d_in, const int* in_sizes, int n_in,
                              void* d_out, int out_size) {
    const int*   tokens = (const int*)  d_in[0];
    const float* eW1    = (const float*)d_in[1];
    const float* eb1    = (const float*)d_in[2];
    const float* eW2    = (const float*)d_in[3];
    const float* eb2    = (const float*)d_in[4];
    const float* hW1    = (const float*)d_in[5];
    const float* hb1    = (const float*)d_in[6];
    const float* hW2    = (const float*)d_in[7];
    const float* hb2    = (const float*)d_in[8];

    float* out    = (float*)d_out;
    float* logits = out;                       // (B,T,V)
    float* sigmas = out + (long)B * T * V;     // (B,T)

    cudaFuncSetAttribute(fused_kernel,
                         cudaFuncAttributeMaxDynamicSharedMemorySize, SMEM_TOTAL);

    precompute_kernel<<<128, 64>>>(eW1, eb1, eW2, eb2, hW1, hb1, hW2, hb2);
    fused_kernel<<<B, 256, SMEM_TOTAL>>>(tokens, logits, sigmas);
}

// round 15
// speedup vs baseline: 1.3683x; 1.3683x over previous
#include <cuda_runtime.h>
#include <math.h>

#define B 256
#define T 2048
#define V 64
#define H 64
#define EOS 2

// Precomputed tables
__device__ float g_gtable[V * 4];
__device__ float g_quad[14 * V];   // [slot s][col v], trace-folded quadratic head

__device__ __forceinline__ float gelu_exact(float x) {
    return 0.5f * x * (1.0f + erff(x * 0.70710678118654752440f));
}

// quaternion as float4: (w,x,y,z) = (q.x,q.y,q.z,q.w)
__device__ __forceinline__ float4 qmul(float4 a, float4 b) {
    float4 r;
    r.x = a.x * b.x - a.y * b.y - a.z * b.z - a.w * b.w;
    r.y = a.x * b.y + a.y * b.x + a.z * b.w - a.w * b.z;
    r.z = a.x * b.z - a.y * b.w + a.z * b.x + a.w * b.y;
    r.w = a.x * b.w + a.y * b.z - a.z * b.y + a.w * b.x;
    return r;
}
__device__ __forceinline__ float4 qnorm(float4 q) {
    float n2 = q.x * q.x + q.y * q.y + q.z * q.z + q.w * q.w;
    float inv = rsqrtf(fmaxf(n2, 1e-24f));
    q.x *= inv; q.y *= inv; q.z *= inv; q.w *= inv;
    return q;
}
__device__ __forceinline__ float4 shfl_up4(float4 v, int delta) {
    float4 r;
    r.x = __shfl_up_sync(0xFFFFFFFFu, v.x, delta);
    r.y = __shfl_up_sync(0xFFFFFFFFu, v.y, delta);
    r.z = __shfl_up_sync(0xFFFFFFFFu, v.z, delta);
    r.w = __shfl_up_sync(0xFFFFFFFFu, v.w, delta);
    return r;
}
__device__ __forceinline__ float wred(float p) {
    #pragma unroll
    for (int off = 16; off > 0; off >>= 1) p += __shfl_down_sync(0xFFFFFFFFu, p, off);
    return p;
}
__device__ __forceinline__ void stcs4(float* p, float4 v) {
    asm volatile("st.global.cs.v4.f32 [%0], {%1,%2,%3,%4};"
                 :: "l"(p), "f"(v.x), "f"(v.y), "f"(v.z), "f"(v.w) : "memory");
}
// acos via A&S 4.4.45: acos(u) = sqrt(1-u) * P(u), u in [0,1], |err| <= 2e-8
__device__ __forceinline__ float acos_poly(float u) {
    float p = fmaf(u, -0.0012624911f, 0.0066700901f);
    p = fmaf(u, p, -0.0170881256f);
    p = fmaf(u, p,  0.0308918810f);
    p = fmaf(u, p, -0.0501743046f);
    p = fmaf(u, p,  0.0889789874f);
    p = fmaf(u, p, -0.2145988016f);
    p = fmaf(u, p,  1.5707963050f);
    return sqrtf(1.0f - u) * p;
}
__device__ __forceinline__ float sig_from_w(float wv) {
    return acos_poly(fminf(fabsf(wv), 1.0f - 1e-7f));
}

// ---------------------------------------------------------------------------
// Kernel 1 (precompute), 128 blocks x 64 threads.  (R4-proven, unchanged)
// ---------------------------------------------------------------------------
__global__ void precompute_kernel(const float* __restrict__ eW1,
                                  const float* __restrict__ eb1,
                                  const float* __restrict__ eW2,
                                  const float* __restrict__ eb2,
                                  const float* __restrict__ hW1,
                                  const float* __restrict__ hb1,
                                  const float* __restrict__ hW2,
                                  const float* __restrict__ hb2) {
    int blk = blockIdx.x;
    int j = threadIdx.x;          // 0..63
    int lane = j & 31, w = j >> 5;

    if (blk < 64) {
        int v = blk;
        float x = eW1[v * H + j] + eb1[j];
        float h = gelu_exact(x);
        float p0 = wred(h * eW2[j * 4 + 0]);
        float p1 = wred(h * eW2[j * 4 + 1]);
        float p2 = wred(h * eW2[j * 4 + 2]);
        float p3 = wred(h * eW2[j * 4 + 3]);
        __shared__ float red[2][4];
        if (lane == 0) { red[w][0] = p0; red[w][1] = p1; red[w][2] = p2; red[w][3] = p3; }
        __syncthreads();
        if (j == 0) {
            float a0 = red[0][0] + red[1][0] + eb2[0];
            float a1 = red[0][1] + red[1][1] + eb2[1];
            float a2 = red[0][2] + red[1][2] + eb2[2];
            float a3 = red[0][3] + red[1][3] + eb2[3];
            float n = sqrtf(a0 * a0 + a1 * a1 + a2 * a2 + a3 * a3);
            float inv = 1.0f / fmaxf(n, 1e-12f);
            float4 g = make_float4(a0 * inv, a1 * inv, a2 * inv, a3 * inv);
            if (v == EOS) g = make_float4(1.0f, 0.0f, 0.0f, 0.0f);
            reinterpret_cast<float4*>(g_gtable)[v] = g;
        }
    } else {
        int v = blk - 64;
        float b  = hb1[j];
        float wv = hW2[j * V + v];
        float w0 = hW1[0 * H + j], w1 = hW1[1 * H + j];
        float w2 = hW1[2 * H + j], w3 = hW1[3 * H + j];
        float sig2 = 0.25f * (w0 * w0 + w1 * w1 + w2 * w2 + w3 * w3);
        float phi = 0.3989422804014327f * expf(-0.5f * b * b);
        float cdf = 0.5f * (1.0f + erff(b * 0.70710678118654752f));
        float g0 = b * cdf;
        float g1 = cdf + b * phi;
        float g2 = 0.5f * (2.0f - b * b) * phi;
        float g3 = -b * (4.0f - b * b) * phi * (1.0f / 6.0f);
        float b2 = b * b;
        float g4 = (-4.0f + 7.0f * b2 - b2 * b2) * phi * (1.0f / 24.0f);
        float e1 = g1 + 3.0f * sig2 * g3;
        float e2 = g2 + 3.0f * sig2 * g4;

        float c[15];
        c[0] = wv * g0;
        float l = wv * e1;
        c[1] = l * w0; c[2] = l * w1; c[3] = l * w2; c[4] = l * w3;
        float q = wv * e2;
        c[5]  = q * w0 * w0;        c[6]  = 2.0f * q * w0 * w1;
        c[7]  = 2.0f * q * w0 * w2; c[8]  = 2.0f * q * w0 * w3;
        c[9]  = q * w1 * w1;        c[10] = 2.0f * q * w1 * w2;
        c[11] = 2.0f * q * w1 * w3; c[12] = q * w2 * w2;
        c[13] = 2.0f * q * w2 * w3; c[14] = q * w3 * w3;

        __shared__ float redq[2][15];
        float tot[15];
        #pragma unroll
        for (int s = 0; s < 15; s++) {
            float r = wred(c[s]);
            if (lane == 0) redq[w][s] = r;
        }
        __syncthreads();
        if (j == 0) {
            #pragma unroll
            for (int s = 0; s < 15; s++) tot[s] = redq[0][s] + redq[1][s];
            tot[0] += hb2[v];
            // fold z^2 slot: c3^2 = 1 - c0^2 - c1^2 - c2^2 (|C| = 1 exactly)
            tot[0]  += tot[14];
            tot[5]  -= tot[14];
            tot[9]  -= tot[14];
            tot[12] -= tot[14];
            #pragma unroll
            for (int s = 0; s < 14; s++) g_quad[s * V + v] = tot[s];
        }
    }
}

// ---------------------------------------------------------------------------
// Kernel 2 (fused): scan + head, one block per batch row. (R12 champion:
// launch_bounds(256,2), norm-free scan, transposed Cbuf, streaming stores,
// acos deferred off the scan critical path.)
// ---------------------------------------------------------------------------
__global__ __launch_bounds__(256, 2) void fused_kernel(const int* __restrict__ tokens,
                                                       float* __restrict__ logits,
                                                       float* __restrict__ sigmas) {
    __shared__ float4 gt[V];
    __shared__ float4 warp_tot[8];
    __shared__ __align__(16) float4 Cbuf[T];   // [i][t] = i*256 + t
    __shared__ __align__(16) float  sbuf[T];   // raw C.x (w components)

    int b = blockIdx.x;
    int t = threadIdx.x;
    int lane = t & 31;
    int w = t >> 5;

    if (t < V) gt[t] = reinterpret_cast<const float4*>(g_gtable)[t];
    __syncthreads();

    // ---- Phase A: scan (8 tokens per thread) ----
    const int4* tp = reinterpret_cast<const int4*>(tokens + b * T + t * 8);
    int4 ta = tp[0];
    int4 tb = tp[1];
    int tok[8] = {ta.x, ta.y, ta.z, ta.w, tb.x, tb.y, tb.z, tb.w};

    // local product (no intermediate norms: unit inputs, drift ~1e-7)
    float4 P = gt[tok[0]];
    #pragma unroll
    for (int i = 1; i < 8; i++) P = qmul(P, gt[tok[i]]);

    // warp Kogge-Stone scan, norm-free
    #pragma unroll
    for (int off = 1; off < 32; off <<= 1) {
        float4 o = shfl_up4(P, off);
        if (lane >= off) P = qmul(o, P);
    }

    if (lane == 31) warp_tot[w] = P;
    float4 laneExcl = shfl_up4(P, 1);
    __syncthreads();

    float4 E = make_float4(1.0f, 0.0f, 0.0f, 0.0f);
    for (int i = 0; i < w; i++) E = qmul(E, warp_tot[i]);
    if (lane > 0) E = qmul(E, laneExcl);
    E = qnorm(E);

    // per-step recompute with per-step normalization (matches reference)
    float4 C = E;
    #pragma unroll
    for (int i = 0; i < 8; i++) {
        C = qnorm(qmul(C, gt[tok[i]]));
        Cbuf[i * 256 + t] = C;                 // 16B thread stride: conflict-free
        sbuf[t * 8 + i] = C.x;                 // raw w; acos deferred to tail
    }
    __syncthreads();

    // ---- Phase B: head. half-warp -> one 256B logits row (coalesced) ----
    int col = lane & 15;
    int half = lane >> 4;

    float4 cf[14];
    const float4* gq = reinterpret_cast<const float4*>(g_quad);
    #pragma unroll
    for (int s = 0; s < 14; s++) cf[s] = gq[s * 16 + col];

    // row = i*16 + w*2 + half; Cbuf index = (row&7)*256 + (row>>3)
    int rlow = (w * 2 + half) & 7;
    int rhigh = (w * 2 + half) >> 3;
    const float4* cbase = Cbuf + rlow * 256 + rhigh;
    float* outp = logits + (long)b * T * V + (long)(w * 2 + half) * V + col * 4;

    #pragma unroll 4
    for (int i = 0; i < 128; i++) {
        float4 Cr = cbase[i * 2];              // broadcast LDS.128

        float m4  = Cr.x * Cr.x, m5  = Cr.x * Cr.y, m6  = Cr.x * Cr.z, m7 = Cr.x * Cr.w;
        float m8  = Cr.y * Cr.y, m9  = Cr.y * Cr.z, m10 = Cr.y * Cr.w;
        float m11 = Cr.z * Cr.z, m12 = Cr.z * Cr.w;

        float4 a = cf[0];
        a.x = fmaf(Cr.x, cf[1].x, a.x);  a.y = fmaf(Cr.x, cf[1].y, a.y);
        a.z = fmaf(Cr.x, cf[1].z, a.z);  a.w = fmaf(Cr.x, cf[1].w, a.w);
        a.x = fmaf(Cr.y, cf[2].x, a.x);  a.y = fmaf(Cr.y, cf[2].y, a.y);
        a.z = fmaf(Cr.y, cf[2].z, a.z);  a.w = fmaf(Cr.y, cf[2].w, a.w);
        a.x = fmaf(Cr.z, cf[3].x, a.x);  a.y = fmaf(Cr.z, cf[3].y, a.y);
        a.z = fmaf(Cr.z, cf[3].z, a.z);  a.w = fmaf(Cr.z, cf[3].w, a.w);
        a.x = fmaf(Cr.w, cf[4].x, a.x);  a.y = fmaf(Cr.w, cf[4].y, a.y);
        a.z = fmaf(Cr.w, cf[4].z, a.z);  a.w = fmaf(Cr.w, cf[4].w, a.w);
        a.x = fmaf(m4,  cf[5].x, a.x);   a.y = fmaf(m4,  cf[5].y, a.y);
        a.z = fmaf(m4,  cf[5].z, a.z);   a.w = fmaf(m4,  cf[5].w, a.w);
        a.x = fmaf(m5,  cf[6].x, a.x);   a.y = fmaf(m5,  cf[6].y, a.y);
        a.z = fmaf(m5,  cf[6].z, a.z);   a.w = fmaf(m5,  cf[6].w, a.w);
        a.x = fmaf(m6,  cf[7].x, a.x);   a.y = fmaf(m6,  cf[7].y, a.y);
        a.z = fmaf(m6,  cf[7].z, a.z);   a.w = fmaf(m6,  cf[7].w, a.w);
        a.x = fmaf(m7,  cf[8].x, a.x);   a.y = fmaf(m7,  cf[8].y, a.y);
        a.z = fmaf(m7,  cf[8].z, a.z);   a.w = fmaf(m7,  cf[8].w, a.w);
        a.x = fmaf(m8,  cf[9].x, a.x);   a.y = fmaf(m8,  cf[9].y, a.y);
        a.z = fmaf(m8,  cf[9].z, a.z);   a.w = fmaf(m8,  cf[9].w, a.w);
        a.x = fmaf(m9,  cf[10].x, a.x);  a.y = fmaf(m9,  cf[10].y, a.y);
        a.z = fmaf(m9,  cf[10].z, a.z);  a.w = fmaf(m9,  cf[10].w, a.w);
        a.x = fmaf(m10, cf[11].x, a.x);  a.y = fmaf(m10, cf[11].y, a.y);
        a.z = fmaf(m10, cf[11].z, a.z);  a.w = fmaf(m10, cf[11].w, a.w);
        a.x = fmaf(m11, cf[12].x, a.x);  a.y = fmaf(m11, cf[12].y, a.y);
        a.z = fmaf(m11, cf[12].z, a.z);  a.w = fmaf(m11, cf[12].w, a.w);
        a.x = fmaf(m12, cf[13].x, a.x);  a.y = fmaf(m12, cf[13].y, a.y);
        a.z = fmaf(m12, cf[13].z, a.z);  a.w = fmaf(m12, cf[13].w, a.w);

        stcs4(outp + (long)i * 16 * V, a);     // streaming store, coalesced
    }

    // ---- sigmas: acos applied at copy-out (off the scan critical path) ----
    const float4* sb4 = reinterpret_cast<const float4*>(sbuf);
    float* so = sigmas + (long)b * T;
    float4 s0 = sb4[t];
    float4 s1 = sb4[t + 256];
    s0.x = sig_from_w(s0.x); s0.y = sig_from_w(s0.y);
    s0.z = sig_from_w(s0.z); s0.w = sig_from_w(s0.w);
    s1.x = sig_from_w(s1.x); s1.y = sig_from_w(s1.y);
    s1.z = sig_from_w(s1.z); s1.w = sig_from_w(s1.w);
    stcs4(so + t * 4, s0);
    stcs4(so + 1024 + t * 4, s1);
}

// ---------------------------------------------------------------------------
extern "C" void kernel_launch(void* const* d_in, const int* in_sizes, int n_in,
                              void* d_out, int out_size) {
    const int*   tokens = (const int*)  d_in[0];
    const float* eW1    = (const float*)d_in[1];
    const float* eb1    = (const float*)d_in[2];
    const float* eW2    = (const float*)d_in[3];
    const float* eb2    = (const float*)d_in[4];
    const float* hW1    = (const float*)d_in[5];
    const float* hb1    = (const float*)d_in[6];
    const float* hW2    = (const float*)d_in[7];
    const float* hb2    = (const float*)d_in[8];

    float* out    = (float*)d_out;
    float* logits = out;                       // (B,T,V)
    float* sigmas = out + (long)B * T * V;     // (B,T)

    precompute_kernel<<<128, 64>>>(eW1, eb1, eW2, eb2, hW1, hb1, hW2, hb2);
    fused_kernel<<<B, 256>>>(tokens, logits, sigmas);
}

// round 16
// speedup vs baseline: 1.3696x; 1.0010x over previous
#include <cuda_runtime.h>
#include <math.h>

#define B 256
#define T 2048
#define V 64
#define H 64
#define EOS 2

// Precomputed tables
__device__ float g_gtable[V * 4];
__device__ float g_quad[14 * V];   // [slot s][col v], trace-folded quadratic head

__device__ __forceinline__ float gelu_exact(float x) {
    return 0.5f * x * (1.0f + erff(x * 0.70710678118654752440f));
}

// quaternion as float4: (w,x,y,z) = (q.x,q.y,q.z,q.w)
__device__ __forceinline__ float4 qmul(float4 a, float4 b) {
    float4 r;
    r.x = a.x * b.x - a.y * b.y - a.z * b.z - a.w * b.w;
    r.y = a.x * b.y + a.y * b.x + a.z * b.w - a.w * b.z;
    r.z = a.x * b.z - a.y * b.w + a.z * b.x + a.w * b.y;
    r.w = a.x * b.w + a.y * b.z - a.z * b.y + a.w * b.x;
    return r;
}
__device__ __forceinline__ float4 qnorm(float4 q) {
    float n2 = q.x * q.x + q.y * q.y + q.z * q.z + q.w * q.w;
    float inv = rsqrtf(fmaxf(n2, 1e-24f));
    q.x *= inv; q.y *= inv; q.z *= inv; q.w *= inv;
    return q;
}
__device__ __forceinline__ float4 shfl_up4(float4 v, int delta) {
    float4 r;
    r.x = __shfl_up_sync(0xFFFFFFFFu, v.x, delta);
    r.y = __shfl_up_sync(0xFFFFFFFFu, v.y, delta);
    r.z = __shfl_up_sync(0xFFFFFFFFu, v.z, delta);
    r.w = __shfl_up_sync(0xFFFFFFFFu, v.w, delta);
    return r;
}
__device__ __forceinline__ float wred(float p) {
    #pragma unroll
    for (int off = 16; off > 0; off >>= 1) p += __shfl_down_sync(0xFFFFFFFFu, p, off);
    return p;
}
__device__ __forceinline__ void stcs4(float* p, float4 v) {
    asm volatile("st.global.cs.v4.f32 [%0], {%1,%2,%3,%4};"
                 :: "l"(p), "f"(v.x), "f"(v.y), "f"(v.z), "f"(v.w) : "memory");
}
// acos via A&S 4.4.45: acos(u) = sqrt(1-u) * P(u), u in [0,1], |err| <= 2e-8
__device__ __forceinline__ float acos_poly(float u) {
    float p = fmaf(u, -0.0012624911f, 0.0066700901f);
    p = fmaf(u, p, -0.0170881256f);
    p = fmaf(u, p,  0.0308918810f);
    p = fmaf(u, p, -0.0501743046f);
    p = fmaf(u, p,  0.0889789874f);
    p = fmaf(u, p, -0.2145988016f);
    p = fmaf(u, p,  1.5707963050f);
    return sqrtf(1.0f - u) * p;
}
__device__ __forceinline__ float sig_from_w(float wv) {
    return acos_poly(fminf(fabsf(wv), 1.0f - 1e-7f));
}
// PDL primitives
__device__ __forceinline__ void pdl_trigger() {
    asm volatile("griddepcontrol.launch_dependents;" ::: "memory");
}
__device__ __forceinline__ void pdl_wait() {
    asm volatile("griddepcontrol.wait;" ::: "memory");
}

// ---------------------------------------------------------------------------
// Kernel 1 (precompute), 128 blocks x 64 threads.  (R4-proven math; adds a
// PDL trigger after each block's global writes are fenced.)
// ---------------------------------------------------------------------------
__global__ void precompute_kernel(const float* __restrict__ eW1,
                                  const float* __restrict__ eb1,
                                  const float* __restrict__ eW2,
                                  const float* __restrict__ eb2,
                                  const float* __restrict__ hW1,
                                  const float* __restrict__ hb1,
                                  const float* __restrict__ hW2,
                                  const float* __restrict__ hb2) {
    int blk = blockIdx.x;
    int j = threadIdx.x;          // 0..63
    int lane = j & 31, w = j >> 5;

    if (blk < 64) {
        int v = blk;
        float x = eW1[v * H + j] + eb1[j];
        float h = gelu_exact(x);
        float p0 = wred(h * eW2[j * 4 + 0]);
        float p1 = wred(h * eW2[j * 4 + 1]);
        float p2 = wred(h * eW2[j * 4 + 2]);
        float p3 = wred(h * eW2[j * 4 + 3]);
        __shared__ float red[2][4];
        if (lane == 0) { red[w][0] = p0; red[w][1] = p1; red[w][2] = p2; red[w][3] = p3; }
        __syncthreads();
        if (j == 0) {
            float a0 = red[0][0] + red[1][0] + eb2[0];
            float a1 = red[0][1] + red[1][1] + eb2[1];
            float a2 = red[0][2] + red[1][2] + eb2[2];
            float a3 = red[0][3] + red[1][3] + eb2[3];
            float n = sqrtf(a0 * a0 + a1 * a1 + a2 * a2 + a3 * a3);
            float inv = 1.0f / fmaxf(n, 1e-12f);
            float4 g = make_float4(a0 * inv, a1 * inv, a2 * inv, a3 * inv);
            if (v == EOS) g = make_float4(1.0f, 0.0f, 0.0f, 0.0f);
            reinterpret_cast<float4*>(g_gtable)[v] = g;
        }
    } else {
        int v = blk - 64;
        float b  = hb1[j];
        float wv = hW2[j * V + v];
        float w0 = hW1[0 * H + j], w1 = hW1[1 * H + j];
        float w2 = hW1[2 * H + j], w3 = hW1[3 * H + j];
        float sig2 = 0.25f * (w0 * w0 + w1 * w1 + w2 * w2 + w3 * w3);
        float phi = 0.3989422804014327f * expf(-0.5f * b * b);
        float cdf = 0.5f * (1.0f + erff(b * 0.70710678118654752f));
        float g0 = b * cdf;
        float g1 = cdf + b * phi;
        float g2 = 0.5f * (2.0f - b * b) * phi;
        float g3 = -b * (4.0f - b * b) * phi * (1.0f / 6.0f);
        float b2 = b * b;
        float g4 = (-4.0f + 7.0f * b2 - b2 * b2) * phi * (1.0f / 24.0f);
        float e1 = g1 + 3.0f * sig2 * g3;
        float e2 = g2 + 3.0f * sig2 * g4;

        float c[15];
        c[0] = wv * g0;
        float l = wv * e1;
        c[1] = l * w0; c[2] = l * w1; c[3] = l * w2; c[4] = l * w3;
        float q = wv * e2;
        c[5]  = q * w0 * w0;        c[6]  = 2.0f * q * w0 * w1;
        c[7]  = 2.0f * q * w0 * w2; c[8]  = 2.0f * q * w0 * w3;
        c[9]  = q * w1 * w1;        c[10] = 2.0f * q * w1 * w2;
        c[11] = 2.0f * q * w1 * w3; c[12] = q * w2 * w2;
        c[13] = 2.0f * q * w2 * w3; c[14] = q * w3 * w3;

        __shared__ float redq[2][15];
        float tot[15];
        #pragma unroll
        for (int s = 0; s < 15; s++) {
            float r = wred(c[s]);
            if (lane == 0) redq[w][s] = r;
        }
        __syncthreads();
        if (j == 0) {
            #pragma unroll
            for (int s = 0; s < 15; s++) tot[s] = redq[0][s] + redq[1][s];
            tot[0] += hb2[v];
            // fold z^2 slot: c3^2 = 1 - c0^2 - c1^2 - c2^2 (|C| = 1 exactly)
            tot[0]  += tot[14];
            tot[5]  -= tot[14];
            tot[9]  -= tot[14];
            tot[12] -= tot[14];
            #pragma unroll
            for (int s = 0; s < 14; s++) g_quad[s * V + v] = tot[s];
        }
    }

    // PDL: this block's table writes are done; fence then allow dependents.
    __syncthreads();
    __threadfence();
    pdl_trigger();
}

// ---------------------------------------------------------------------------
// Kernel 2 (fused): scan + head, one block per batch row. (R12 champion body;
// token loads issued BEFORE the PDL wait so they overlap precompute.)
// ---------------------------------------------------------------------------
__global__ __launch_bounds__(256, 2) void fused_kernel(const int* __restrict__ tokens,
                                                       float* __restrict__ logits,
                                                       float* __restrict__ sigmas) {
    __shared__ float4 gt[V];
    __shared__ float4 warp_tot[8];
    __shared__ __align__(16) float4 Cbuf[T];   // [i][t] = i*256 + t
    __shared__ __align__(16) float  sbuf[T];   // raw C.x (w components)

    int b = blockIdx.x;
    int t = threadIdx.x;
    int lane = t & 31;
    int w = t >> 5;

    // issue token loads first — independent of precompute's output
    const int4* tp = reinterpret_cast<const int4*>(tokens + b * T + t * 8);
    int4 ta = tp[0];
    int4 tb = tp[1];

    // now wait for precompute's tables to be published
    pdl_wait();

    if (t < V) gt[t] = reinterpret_cast<const float4*>(g_gtable)[t];
    __syncthreads();

    // ---- Phase A: scan (8 tokens per thread) ----
    int tok[8] = {ta.x, ta.y, ta.z, ta.w, tb.x, tb.y, tb.z, tb.w};

    // local product (no intermediate norms: unit inputs, drift ~1e-7)
    float4 P = gt[tok[0]];
    #pragma unroll
    for (int i = 1; i < 8; i++) P = qmul(P, gt[tok[i]]);

    // warp Kogge-Stone scan, norm-free
    #pragma unroll
    for (int off = 1; off < 32; off <<= 1) {
        float4 o = shfl_up4(P, off);
        if (lane >= off) P = qmul(o, P);
    }

    if (lane == 31) warp_tot[w] = P;
    float4 laneExcl = shfl_up4(P, 1);
    __syncthreads();

    float4 E = make_float4(1.0f, 0.0f, 0.0f, 0.0f);
    for (int i = 0; i < w; i++) E = qmul(E, warp_tot[i]);
    if (lane > 0) E = qmul(E, laneExcl);
    E = qnorm(E);

    // per-step recompute with per-step normalization (matches reference)
    float4 C = E;
    #pragma unroll
    for (int i = 0; i < 8; i++) {
        C = qnorm(qmul(C, gt[tok[i]]));
        Cbuf[i * 256 + t] = C;                 // 16B thread stride: conflict-free
        sbuf[t * 8 + i] = C.x;                 // raw w; acos deferred to tail
    }
    __syncthreads();

    // ---- Phase B: head. half-warp -> one 256B logits row (coalesced) ----
    int col = lane & 15;
    int half = lane >> 4;

    float4 cf[14];
    const float4* gq = reinterpret_cast<const float4*>(g_quad);
    #pragma unroll
    for (int s = 0; s < 14; s++) cf[s] = gq[s * 16 + col];

    // row = i*16 + w*2 + half; Cbuf index = (row&7)*256 + (row>>3)
    int rlow = (w * 2 + half) & 7;
    int rhigh = (w * 2 + half) >> 3;
    const float4* cbase = Cbuf + rlow * 256 + rhigh;
    float* outp = logits + (long)b * T * V + (long)(w * 2 + half) * V + col * 4;

    #pragma unroll 4
    for (int i = 0; i < 128; i++) {
        float4 Cr = cbase[i * 2];              // broadcast LDS.128

        float m4  = Cr.x * Cr.x, m5  = Cr.x * Cr.y, m6  = Cr.x * Cr.z, m7 = Cr.x * Cr.w;
        float m8  = Cr.y * Cr.y, m9  = Cr.y * Cr.z, m10 = Cr.y * Cr.w;
        float m11 = Cr.z * Cr.z, m12 = Cr.z * Cr.w;

        float4 a = cf[0];
        a.x = fmaf(Cr.x, cf[1].x, a.x);  a.y = fmaf(Cr.x, cf[1].y, a.y);
        a.z = fmaf(Cr.x, cf[1].z, a.z);  a.w = fmaf(Cr.x, cf[1].w, a.w);
        a.x = fmaf(Cr.y, cf[2].x, a.x);  a.y = fmaf(Cr.y, cf[2].y, a.y);
        a.z = fmaf(Cr.y, cf[2].z, a.z);  a.w = fmaf(Cr.y, cf[2].w, a.w);
        a.x = fmaf(Cr.z, cf[3].x, a.x);  a.y = fmaf(Cr.z, cf[3].y, a.y);
        a.z = fmaf(Cr.z, cf[3].z, a.z);  a.w = fmaf(Cr.z, cf[3].w, a.w);
        a.x = fmaf(Cr.w, cf[4].x, a.x);  a.y = fmaf(Cr.w, cf[4].y, a.y);
        a.z = fmaf(Cr.w, cf[4].z, a.z);  a.w = fmaf(Cr.w, cf[4].w, a.w);
        a.x = fmaf(m4,  cf[5].x, a.x);   a.y = fmaf(m4,  cf[5].y, a.y);
        a.z = fmaf(m4,  cf[5].z, a.z);   a.w = fmaf(m4,  cf[5].w, a.w);
        a.x = fmaf(m5,  cf[6].x, a.x);   a.y = fmaf(m5,  cf[6].y, a.y);
        a.z = fmaf(m5,  cf[6].z, a.z);   a.w = fmaf(m5,  cf[6].w, a.w);
        a.x = fmaf(m6,  cf[7].x, a.x);   a.y = fmaf(m6,  cf[7].y, a.y);
        a.z = fmaf(m6,  cf[7].z, a.z);   a.w = fmaf(m6,  cf[7].w, a.w);
        a.x = fmaf(m7,  cf[8].x, a.x);   a.y = fmaf(m7,  cf[8].y, a.y);
        a.z = fmaf(m7,  cf[8].z, a.z);   a.w = fmaf(m7,  cf[8].w, a.w);
        a.x = fmaf(m8,  cf[9].x, a.x);   a.y = fmaf(m8,  cf[9].y, a.y);
        a.z = fmaf(m8,  cf[9].z, a.z);   a.w = fmaf(m8,  cf[9].w, a.w);
        a.x = fmaf(m9,  cf[10].x, a.x);  a.y = fmaf(m9,  cf[10].y, a.y);
        a.z = fmaf(m9,  cf[10].z, a.z);  a.w = fmaf(m9,  cf[10].w, a.w);
        a.x = fmaf(m10, cf[11].x, a.x);  a.y = fmaf(m10, cf[11].y, a.y);
        a.z = fmaf(m10, cf[11].z, a.z);  a.w = fmaf(m10, cf[11].w, a.w);
        a.x = fmaf(m11, cf[12].x, a.x);  a.y = fmaf(m11, cf[12].y, a.y);
        a.z = fmaf(m11, cf[12].z, a.z);  a.w = fmaf(m11, cf[12].w, a.w);
        a.x = fmaf(m12, cf[13].x, a.x);  a.y = fmaf(m12, cf[13].y, a.y);
        a.z = fmaf(m12, cf[13].z, a.z);  a.w = fmaf(m12, cf[13].w, a.w);

        stcs4(outp + (long)i * 16 * V, a);     // streaming store, coalesced
    }

    // ---- sigmas: acos applied at copy-out (off the scan critical path) ----
    const float4* sb4 = reinterpret_cast<const float4*>(sbuf);
    float* so = sigmas + (long)b * T;
    float4 s0 = sb4[t];
    float4 s1 = sb4[t + 256];
    s0.x = sig_from_w(s0.x); s0.y = sig_from_w(s0.y);
    s0.z = sig_from_w(s0.z); s0.w = sig_from_w(s0.w);
    s1.x = sig_from_w(s1.x); s1.y = sig_from_w(s1.y);
    s1.z = sig_from_w(s1.z); s1.w = sig_from_w(s1.w);
    stcs4(so + t * 4, s0);
    stcs4(so + 1024 + t * 4, s1);
}

// ---------------------------------------------------------------------------
extern "C" void kernel_launch(void* const* d_in, const int* in_sizes, int n_in,
                              void* d_out, int out_size) {
    const int*   tokens = (const int*)  d_in[0];
    const float* eW1    = (const float*)d_in[1];
    const float* eb1    = (const float*)d_in[2];
    const float* eW2    = (const float*)d_in[3];
    const float* eb2    = (const float*)d_in[4];
    const float* hW1    = (const float*)d_in[5];
    const float* hb1    = (const float*)d_in[6];
    const float* hW2    = (const float*)d_in[7];
    const float* hb2    = (const float*)d_in[8];

    float* out    = (float*)d_out;
    float* logits = out;                       // (B,T,V)
    float* sigmas = out + (long)B * T * V;     // (B,T)

    precompute_kernel<<<128, 64>>>(eW1, eb1, eW2, eb2, hW1, hb1, hW2, hb2);

    // fused kernel launches programmatically-dependent on precompute:
    // blocks start (and do their token LDGs) while precompute drains.
    cudaLaunchConfig_t cfg = {};
    cfg.gridDim = dim3(B, 1, 1);
    cfg.blockDim = dim3(256, 1, 1);
    cfg.dynamicSmemBytes = 0;
    cfg.stream = 0;
    cudaLaunchAttribute attrs[1];
    attrs[0].id = cudaLaunchAttributeProgrammaticStreamSerialization;
    attrs[0].val.programmaticStreamSerializationAllowed = 1;
    cfg.attrs = attrs;
    cfg.numAttrs = 1;
    cudaLaunchKernelEx(&cfg, fused_kernel, tokens, logits, sigmas);
}